// round 14
// baseline (speedup 1.0000x reference)
#include <cuda_runtime.h>
#include <cuda_fp16.h>

// Problem-fixed maxima (from setup_inputs): N=100000, E=1600000, dims 128->32->32->1.
#define MAXN 100000
#define MAXE 1600000
#define SCAN_B 512
#define MAXNB ((MAXN + SCAN_B - 1) / SCAN_B)       // 196
#define MAXW  ((MAXN + 7) / 8)                     // 12500 warp-groups
#define MAXNBW ((MAXW + SCAN_B - 1) / SCAN_B)      // 25

// ---- scratch (device globals; allocation-free per harness rules) ----
// Zero-initialized at module load; every launch restores g_deg==0 and both
// scan counters==0 (scatter decrements deg to 0; scan finales reset counters),
// so graph replays see identical initial state.
__device__ __half g_Zh[MAXN * 32];   // layer-1 z (fp16 for gather bandwidth)
__device__ __half g_Z2h[MAXN * 32];  // layer-2 z (fp16)
__device__ float g_Zs[MAXN];         // layer-3 z (scalar, fp32)
__device__ float g_SS1[MAXN], g_SD1[MAXN];
__device__ float g_SS2[MAXN], g_SD2[MAXN];
__device__ float g_SS3[MAXN], g_SD3[MAXN];
__device__ int   g_deg[MAXN];        // degree counters (return to 0 each launch)
__device__ int   g_row[MAXN + 1];    // block-local exclusive scan of deg
__device__ int   g_bsum[MAXNB];      // exclusive-scanned block sums
__device__ int   g_woff[MAXW + 8];   // block-local excl scan of 8*maxdeg per warp-group
__device__ int   g_wsum[MAXNBW];     // exclusive-scanned block sums (warp scan)
__device__ int   g_ell[8 * MAXE];    // ELL-interleaved src ids (51MB, bounded by 8E)
__device__ int   g_scan_ctr;         // decoupled-scan counter (self-resetting)
__device__ int   g_scan_ctrW;        // decoupled warp-scan counter (self-resetting)

// row_final(i)  = g_row[i]  + g_bsum[i >> 9]   (0..N; g_row[N] patched)
// woff_final(w) = g_woff[w] + g_wsum[w >> 9]   (base of warp-group w's ELL region)

// ===========================================================================
// Fused: dst histogram (blocks [0, histBlocks)) + layer-1 node GEMM
// (blocks [histBlocks, ...)). Independent work co-scheduled on the chip.
// GEMM: z = feat@W1 (stored fp16), s_src1/s_dst1. dout=32, 4 nodes per warp.
// ===========================================================================
__global__ void __launch_bounds__(256)
hist_gemm_kernel(const int* __restrict__ dst, int E, int histBlocks,
                 const float* __restrict__ feat,
                 const float* __restrict__ W,
                 const float* __restrict__ a,
                 int N, int din)
{
    if (blockIdx.x < histBlocks) {
        int e = blockIdx.x * blockDim.x + threadIdx.x;
        if (e < E) atomicAdd(&g_deg[dst[e]], 1);
        return;
    }
    int bid = blockIdx.x - histBlocks;

    extern __shared__ float sh[];
    float* Ws = sh;                // din*32
    float* as = Ws + din * 32;     // 64
    float* hs = as + 64;           // WPB * 4 * din

    int tid = threadIdx.x;
    for (int i = tid; i < din * 32; i += blockDim.x) Ws[i] = W[i];
    for (int i = tid; i < 64; i += blockDim.x) as[i] = a[i];
    __syncthreads();

    int lane = tid & 31;
    int wrp  = tid >> 5;
    int WPB  = blockDim.x >> 5;
    float* hw = hs + wrp * 4 * din;

    int n0 = (bid * WPB + wrp) * 4;
    if (n0 >= N) return;
    int cnt = (N - n0 < 4) ? (N - n0) : 4;

    for (int t = 0; t < cnt; t++) {
        const float* hr = feat + (long long)(n0 + t) * din;
        for (int k = lane; k < din; k += 32) hw[t * din + k] = hr[k];
    }
    for (int t = cnt; t < 4; t++)
        for (int k = lane; k < din; k += 32) hw[t * din + k] = 0.f;
    __syncwarp();

    float z0 = 0.f, z1 = 0.f, z2 = 0.f, z3 = 0.f;
    #pragma unroll 8
    for (int k = 0; k < din; k++) {
        float wv = Ws[k * 32 + lane];
        z0 = fmaf(hw[k],           wv, z0);
        z1 = fmaf(hw[din + k],     wv, z1);
        z2 = fmaf(hw[2 * din + k], wv, z2);
        z3 = fmaf(hw[3 * din + k], wv, z3);
    }
    float zz[4] = {z0, z1, z2, z3};
    float aS = as[lane], aD = as[32 + lane];
    for (int t = 0; t < cnt; t++) {
        int n = n0 + t;
        g_Zh[n * 32 + lane] = __float2half(zz[t]);
        float ps = zz[t] * aS, pd = zz[t] * aD;
        #pragma unroll
        for (int o = 16; o; o >>= 1) {
            ps += __shfl_down_sync(0xffffffffu, ps, o);
            pd += __shfl_down_sync(0xffffffffu, pd, o);
        }
        if (lane == 0) { g_SS1[n] = ps; g_SD1[n] = pd; }
    }
}

// ===========================================================================
// Fused two-segment scan kernel (both segments depend only on g_deg):
//  blocks [0, NB):       per-node exclusive scan -> g_row / g_bsum (decoupled)
//  blocks [NB, NB+NBW):  per-warp-group 8*maxdeg scan -> g_woff / g_wsum
// Both finales reset their counters for graph-replay safety.
// ===========================================================================
__global__ void __launch_bounds__(SCAN_B)
scan_both_kernel(int N, int E, int NB, int NW, int NBW)
{
    __shared__ int sh[SCAN_B];
    __shared__ int flagS;
    int tid = threadIdx.x;

    if (blockIdx.x < NB) {
        int i = blockIdx.x * SCAN_B + tid;
        int v = (i < N) ? g_deg[i] : 0;
        sh[tid] = v;
        __syncthreads();
        #pragma unroll
        for (int o = 1; o < SCAN_B; o <<= 1) {
            int t = (tid >= o) ? sh[tid - o] : 0;
            __syncthreads();
            sh[tid] += t;
            __syncthreads();
        }
        if (i < N) g_row[i] = sh[tid] - v;          // exclusive within block
        if (tid == SCAN_B - 1) g_bsum[blockIdx.x] = sh[tid];

        __threadfence();
        if (tid == 0) flagS = (atomicAdd(&g_scan_ctr, 1) == NB - 1);
        __syncthreads();
        if (flagS) {
            int bv = (tid < NB) ? g_bsum[tid] : 0;
            sh[tid] = bv;
            __syncthreads();
            #pragma unroll
            for (int o = 1; o < SCAN_B; o <<= 1) {
                int t = (tid >= o) ? sh[tid - o] : 0;
                __syncthreads();
                sh[tid] += t;
                __syncthreads();
            }
            int excl = sh[tid] - bv;
            if (tid < NB) g_bsum[tid] = excl;       // exclusive block offsets
            if (tid == (N >> 9)) g_row[N] = E - excl;  // row_final(N) == E
            if (tid == 0) g_scan_ctr = 0;           // restore invariant
        }
    } else {
        int wb  = blockIdx.x - NB;
        int wid = wb * SCAN_B + tid;
        int md = 0;
        if (wid < NW) {
            int n0 = wid * 8;
            int lim = min(8, N - n0);
            for (int k = 0; k < lim; k++) md = max(md, g_deg[n0 + k]);
        }
        int v = md * 8;                             // ELL bytes for this group
        sh[tid] = v;
        __syncthreads();
        #pragma unroll
        for (int o = 1; o < SCAN_B; o <<= 1) {
            int t = (tid >= o) ? sh[tid - o] : 0;
            __syncthreads();
            sh[tid] += t;
            __syncthreads();
        }
        if (wid < NW) g_woff[wid] = sh[tid] - v;    // exclusive within block
        if (tid == SCAN_B - 1) g_wsum[wb] = sh[tid];

        __threadfence();
        if (tid == 0) flagS = (atomicAdd(&g_scan_ctrW, 1) == NBW - 1);
        __syncthreads();
        if (flagS) {
            int bv = (tid < NBW) ? g_wsum[tid] : 0;
            sh[tid] = bv;
            __syncthreads();
            #pragma unroll
            for (int o = 1; o < SCAN_B; o <<= 1) {
                int t = (tid >= o) ? sh[tid - o] : 0;
                __syncthreads();
                sh[tid] += t;
                __syncthreads();
            }
            if (tid < NBW) g_wsum[tid] = sh[tid] - bv;  // exclusive
            if (tid == 0) g_scan_ctrW = 0;          // restore invariant
        }
    }
}

// ===========================================================================
// Scatter into ELL-interleaved layout. Slot via decrement of g_deg (restores
// g_deg==0 for the next replay). Position: woff(d/8) + slot*8 + (d%8) ->
// at gather iteration t, a warp's 8 groups read 8 CONSECUTIVE ints.
// ===========================================================================
__global__ void __launch_bounds__(256)
scatter_kernel(const int* __restrict__ src, const int* __restrict__ dst, int E)
{
    int e = blockIdx.x * blockDim.x + threadIdx.x;
    if (e < E) {
        int d = dst[e];
        int c = atomicAdd(&g_deg[d], -1) - 1;       // 0..deg-1, deg -> 0
        int w8 = d >> 3;
        int pos = g_woff[w8] + g_wsum[w8 >> 9] + c * 8 + (d & 7);
        g_ell[pos] = src[e];
    }
}

// ===========================================================================
// Gather core: 8 dst nodes per warp, 4 lanes per node, fp16 Z rows (64B/node),
// ELL edge list (esrc = 1 coalesced 32B read per warp-iteration), no inner
// shuffles, 2-way unrolled with per-edge predication (masked lanes generate
// no wavefronts).
// ===========================================================================
#define FMA8(W, R)                                                             \
    {                                                                          \
        __half2* hp = (__half2*)&(R);                                          \
        float2 f0 = __half22float2(hp[0]);                                     \
        float2 f1 = __half22float2(hp[1]);                                     \
        float2 f2 = __half22float2(hp[2]);                                     \
        float2 f3 = __half22float2(hp[3]);                                     \
        acc0.x = fmaf(W, f0.x, acc0.x); acc0.y = fmaf(W, f0.y, acc0.y);        \
        acc0.z = fmaf(W, f1.x, acc0.z); acc0.w = fmaf(W, f1.y, acc0.w);        \
        acc1.x = fmaf(W, f2.x, acc1.x); acc1.y = fmaf(W, f2.y, acc1.y);        \
        acc1.z = fmaf(W, f3.x, acc1.z); acc1.w = fmaf(W, f3.y, acc1.w);        \
    }

#define GATHER_EDGE(TT, SScur)                                                 \
        if ((TT) < cnt) {                                                      \
            int s0 = g_ell[ebase + (TT) * 8 + grp];                            \
            float x0 = SScur[s0] + sd;                                         \
            uint4 r0 = Zv[s0 * 4 + l4];                                        \
            x0 = (x0 > 0.f) ? x0 : 0.01f * x0;                                 \
            float w0 = __expf(x0);                                             \
            den += w0;                                                         \
            FMA8(w0, r0)                                                       \
        }

#define GATHER8_CORE(SScur, SDcur, ZHALF)                                      \
    int lane = threadIdx.x & 31;                                               \
    int l4   = lane & 3;                                                       \
    int grp  = lane >> 2;                                                      \
    int warpid = blockIdx.x * (blockDim.x >> 5) + (threadIdx.x >> 5);          \
    int n = warpid * 8 + grp;                                                  \
    bool valid = (n < N);                                                      \
    int cnt = 0; float sd = 0.f;                                               \
    if (valid) {                                                               \
        cnt = (g_row[n + 1] + g_bsum[(n + 1) >> 9])                            \
            - (g_row[n] + g_bsum[n >> 9]);                                     \
        sd  = SDcur[n];                                                        \
    }                                                                          \
    int ebase = g_woff[warpid] + g_wsum[warpid >> 9];                          \
    int cntmax = cnt;                                                          \
    cntmax = max(cntmax, __shfl_xor_sync(0xffffffffu, cntmax, 4));             \
    cntmax = max(cntmax, __shfl_xor_sync(0xffffffffu, cntmax, 8));             \
    cntmax = max(cntmax, __shfl_xor_sync(0xffffffffu, cntmax, 16));            \
    const uint4* Zv = (const uint4*)ZHALF;                                     \
    float4 acc0 = make_float4(0.f, 0.f, 0.f, 0.f);                             \
    float4 acc1 = make_float4(0.f, 0.f, 0.f, 0.f);                             \
    float den = 0.f;                                                           \
    int t = 0;                                                                 \
    for (; t + 2 <= cntmax; t += 2) {                                          \
        GATHER_EDGE(t, SScur)                                                  \
        GATHER_EDGE(t + 1, SScur)                                              \
    }                                                                          \
    if (t < cntmax) { GATHER_EDGE(t, SScur) }                                  \
    float inv = 1.f / fmaxf(den, 1e-9f);                                       \
    float ha[8];                                                               \
    ha[0] = fmaxf(acc0.x * inv, 0.f); ha[1] = fmaxf(acc0.y * inv, 0.f);        \
    ha[2] = fmaxf(acc0.z * inv, 0.f); ha[3] = fmaxf(acc0.w * inv, 0.f);        \
    ha[4] = fmaxf(acc1.x * inv, 0.f); ha[5] = fmaxf(acc1.y * inv, 0.f);        \
    ha[6] = fmaxf(acc1.z * inv, 0.f); ha[7] = fmaxf(acc1.w * inv, 0.f);
// ha holds relu'd features (8*l4 .. 8*l4+7) of node n.

// ---------------------------------------------------------------------------
// Gather layer 1 + fused layer-2 node GEMM (z2 = h@W2, s_src2, s_dst2).
// ---------------------------------------------------------------------------
__global__ void __launch_bounds__(256)
gather_fuse_L1L2_kernel(int N, const float* __restrict__ W2,
                        const float* __restrict__ a2)
{
    __shared__ float W2s[32 * 32];
    __shared__ float a2s[64];
    int tid0 = threadIdx.x;
    for (int i = tid0; i < 32 * 32; i += blockDim.x) W2s[i] = W2[i];
    if (tid0 < 64) a2s[tid0] = a2[tid0];
    __syncthreads();

    GATHER8_CORE(g_SS1, g_SD1, g_Zh)

    // z2[8 outputs: 8*l4 .. 8*l4+7] = sum_k h[k] * W2[k][outputs]
    const float4* W2v = (const float4*)W2s;    // row k = 8 float4s
    float z2[8];
    #pragma unroll
    for (int j = 0; j < 8; j++) z2[j] = 0.f;
    int gbase = lane & 28;                      // first lane of this group
    #pragma unroll
    for (int sl = 0; sl < 4; sl++) {
        #pragma unroll
        for (int i = 0; i < 8; i++) {
            float hk = __shfl_sync(0xffffffffu, ha[i], gbase | sl);
            int k = sl * 8 + i;
            float4 wA = W2v[k * 8 + 2 * l4];
            float4 wB = W2v[k * 8 + 2 * l4 + 1];
            z2[0] = fmaf(hk, wA.x, z2[0]); z2[1] = fmaf(hk, wA.y, z2[1]);
            z2[2] = fmaf(hk, wA.z, z2[2]); z2[3] = fmaf(hk, wA.w, z2[3]);
            z2[4] = fmaf(hk, wB.x, z2[4]); z2[5] = fmaf(hk, wB.y, z2[5]);
            z2[6] = fmaf(hk, wB.z, z2[6]); z2[7] = fmaf(hk, wB.w, z2[7]);
        }
    }
    float ps = 0.f, pd = 0.f;
    #pragma unroll
    for (int j = 0; j < 8; j++) {
        ps = fmaf(z2[j], a2s[8 * l4 + j], ps);
        pd = fmaf(z2[j], a2s[32 + 8 * l4 + j], pd);
    }
    ps += __shfl_xor_sync(0xffffffffu, ps, 1);
    ps += __shfl_xor_sync(0xffffffffu, ps, 2);
    pd += __shfl_xor_sync(0xffffffffu, pd, 1);
    pd += __shfl_xor_sync(0xffffffffu, pd, 2);
    if (valid) {
        __half2 p0 = __floats2half2_rn(z2[0], z2[1]);
        __half2 p1 = __floats2half2_rn(z2[2], z2[3]);
        __half2 p2 = __floats2half2_rn(z2[4], z2[5]);
        __half2 p3 = __floats2half2_rn(z2[6], z2[7]);
        uint4 raw;
        raw.x = *reinterpret_cast<unsigned int*>(&p0);
        raw.y = *reinterpret_cast<unsigned int*>(&p1);
        raw.z = *reinterpret_cast<unsigned int*>(&p2);
        raw.w = *reinterpret_cast<unsigned int*>(&p3);
        ((uint4*)g_Z2h)[n * 4 + l4] = raw;
        if (l4 == 0) { g_SS2[n] = ps; g_SD2[n] = pd; }
    }
}

// ---------------------------------------------------------------------------
// Gather layer 2 + fused layer-3 node GEMM (scalar z3 = h.W3, s3 scalars).
// ---------------------------------------------------------------------------
__global__ void __launch_bounds__(256)
gather_fuse_L2L3_kernel(int N, const float* __restrict__ W3,
                        const float* __restrict__ a3)
{
    __shared__ float W3s[32];
    __shared__ float a3s[2];
    int tid0 = threadIdx.x;
    if (tid0 < 32) W3s[tid0] = W3[tid0];
    if (tid0 < 2)  a3s[tid0] = a3[tid0];
    __syncthreads();

    GATHER8_CORE(g_SS2, g_SD2, g_Z2h)

    float z3 = 0.f;
    #pragma unroll
    for (int i = 0; i < 8; i++) z3 = fmaf(ha[i], W3s[8 * l4 + i], z3);
    z3 += __shfl_xor_sync(0xffffffffu, z3, 1);
    z3 += __shfl_xor_sync(0xffffffffu, z3, 2);
    if (valid && l4 == 0) {
        g_Zs[n]  = z3;
        g_SS3[n] = z3 * a3s[0];
        g_SD3[n] = z3 * a3s[1];
    }
}

// ---------------------------------------------------------------------------
// Final gather (dout=1): 8 nodes/warp, 4 lanes split each node's edges via the
// ELL layout (a warp-iteration reads 32 consecutive ints = 1 line), normalize
// + sigmoid -> output.
// ---------------------------------------------------------------------------
__global__ void __launch_bounds__(256)
gather1_kernel(int N, float* __restrict__ out)
{
    int lane = threadIdx.x & 31;
    int l4   = lane & 3;
    int grp  = lane >> 2;
    int warpid = blockIdx.x * (blockDim.x >> 5) + (threadIdx.x >> 5);
    int n = warpid * 8 + grp;
    bool valid = (n < N);
    int cnt = 0; float sd = 0.f;
    if (valid) {
        cnt = (g_row[n + 1] + g_bsum[(n + 1) >> 9])
            - (g_row[n] + g_bsum[n >> 9]);
        sd  = g_SD3[n];
    }
    int ebase = g_woff[warpid] + g_wsum[warpid >> 9];

    float acc = 0.f, den = 0.f;
    for (int i = l4; i < cnt; i += 4) {
        int s = g_ell[ebase + i * 8 + grp];
        float x = g_SS3[s] + sd;
        x = (x > 0.f) ? x : 0.01f * x;
        float w = __expf(x);
        den += w;
        acc = fmaf(w, g_Zs[s], acc);
    }
    den += __shfl_xor_sync(0xffffffffu, den, 1);
    den += __shfl_xor_sync(0xffffffffu, den, 2);
    acc += __shfl_xor_sync(0xffffffffu, acc, 1);
    acc += __shfl_xor_sync(0xffffffffu, acc, 2);
    if (valid && l4 == 0) {
        float v = acc / fmaxf(den, 1e-9f);
        out[n] = 1.f / (1.f + __expf(-v));
    }
}

// ===========================================================================
extern "C" void kernel_launch(void* const* d_in, const int* in_sizes, int n_in,
                              void* d_out, int out_size)
{
    const float* feat = (const float*)d_in[0];
    const int*   src  = (const int*)d_in[1];
    const int*   dst  = (const int*)d_in[2];
    const float* W1   = (const float*)d_in[3];
    const float* a1   = (const float*)d_in[4];
    const float* W2   = (const float*)d_in[5];
    const float* a2   = (const float*)d_in[6];
    const float* W3   = (const float*)d_in[7];
    const float* a3   = (const float*)d_in[8];

    const int E    = in_sizes[1];
    const int d1   = in_sizes[4] / 2;          // 32
    const int din1 = in_sizes[3] / d1;         // 128
    const int N    = in_sizes[0] / din1;       // 100000

    const int NT  = 256;
    const int WPB = NT / 32;                   // 8 warps/block
    float* out = (float*)d_out;

    // ---- fused dst-histogram + layer-1 node GEMM ----
    const int histBlocks = (E + NT - 1) / NT;
    const int gemmBlocks = (N + 4 * WPB - 1) / (4 * WPB);   // 4 nodes/warp
    {
        size_t shm = (size_t)(din1 * 32 + 64 + WPB * 4 * din1) * sizeof(float);
        hist_gemm_kernel<<<histBlocks + gemmBlocks, NT, shm>>>(
            dst, E, histBlocks, feat, W1, a1, N, din1);
    }

    // ---- fused node-scan + warp-group ELL scan, then ELL scatter ----
    const int NB  = (N + SCAN_B - 1) / SCAN_B;
    const int NW  = (N + 7) / 8;
    const int NBW = (NW + SCAN_B - 1) / SCAN_B;
    scan_both_kernel<<<NB + NBW, SCAN_B>>>(N, E, NB, NW, NBW);
    scatter_kernel<<<histBlocks, NT>>>(src, dst, E);

    // ---- Gather chains (8 nodes/warp, 4 lanes/node, fp16 Z, ELL edges) ----
    const int octs = (N + 7) / 8;
    const int gBlocks = (octs + WPB - 1) / WPB;
    gather_fuse_L1L2_kernel<<<gBlocks, NT>>>(N, W2, a2);
    gather_fuse_L2L3_kernel<<<gBlocks, NT>>>(N, W3, a3);
    gather1_kernel<<<gBlocks, NT>>>(N, out);
}

// round 15
// speedup vs baseline: 1.0729x; 1.0729x over previous
#include <cuda_runtime.h>
#include <cuda_fp16.h>

// Problem-fixed maxima (from setup_inputs): N=100000, E=1600000, dims 128->32->32->1.
#define MAXN 100000
#define MAXE 1600000
#define SCAN_B 512
#define MAXNB ((MAXN + SCAN_B - 1) / SCAN_B)   // 196

// ---- scratch (device globals; allocation-free per harness rules) ----
// Zero-initialized at module load; every launch restores g_deg==0 and
// g_scan_ctr==0 (scatter decrements deg back to 0; scan1 last block resets ctr),
// so graph replays see identical initial state.
__device__ __half g_Zh[MAXN * 32];   // layer-1 z (fp16 for gather bandwidth)
__device__ __half g_Z2h[MAXN * 32];  // layer-2 z (fp16)
__device__ float g_Zs[MAXN];         // layer-3 z (scalar, fp32)
__device__ float g_SS1[MAXN], g_SD1[MAXN];
__device__ float g_SS2[MAXN], g_SD2[MAXN];
__device__ float g_SS3[MAXN], g_SD3[MAXN];
__device__ int   g_deg[MAXN];        // degree counters (return to 0 each launch)
__device__ int   g_row[MAXN + 1];    // block-local exclusive scan of deg
__device__ int   g_bsum[MAXNB];      // exclusive-scanned block sums
__device__ int   g_esrc[MAXE];       // dst-sorted src ids (CSR order)
__device__ int   g_scan_ctr;         // decoupled-scan counter (self-resetting)

// row_final(i) = g_row[i] + g_bsum[i >> 9]  (valid for 0..N; g_row[N] patched)

// ===========================================================================
// Fused: dst histogram (blocks [0, histBlocks)) + layer-1 node GEMM
// (blocks [histBlocks, ...)). Independent work co-scheduled on the chip.
// GEMM: z = feat@W1 (stored fp16), s_src1/s_dst1. dout=32, 4 nodes per warp.
// ===========================================================================
__global__ void __launch_bounds__(256)
hist_gemm_kernel(const int* __restrict__ dst, int E, int histBlocks,
                 const float* __restrict__ feat,
                 const float* __restrict__ W,
                 const float* __restrict__ a,
                 int N, int din)
{
    if (blockIdx.x < histBlocks) {
        int e = blockIdx.x * blockDim.x + threadIdx.x;
        if (e < E) atomicAdd(&g_deg[dst[e]], 1);
        return;
    }
    int bid = blockIdx.x - histBlocks;

    extern __shared__ float sh[];
    float* Ws = sh;                // din*32
    float* as = Ws + din * 32;     // 64
    float* hs = as + 64;           // WPB * 4 * din

    int tid = threadIdx.x;
    for (int i = tid; i < din * 32; i += blockDim.x) Ws[i] = W[i];
    for (int i = tid; i < 64; i += blockDim.x) as[i] = a[i];
    __syncthreads();

    int lane = tid & 31;
    int wrp  = tid >> 5;
    int WPB  = blockDim.x >> 5;
    float* hw = hs + wrp * 4 * din;

    int n0 = (bid * WPB + wrp) * 4;
    if (n0 >= N) return;
    int cnt = (N - n0 < 4) ? (N - n0) : 4;

    for (int t = 0; t < cnt; t++) {
        const float* hr = feat + (long long)(n0 + t) * din;
        for (int k = lane; k < din; k += 32) hw[t * din + k] = hr[k];
    }
    for (int t = cnt; t < 4; t++)
        for (int k = lane; k < din; k += 32) hw[t * din + k] = 0.f;
    __syncwarp();

    float z0 = 0.f, z1 = 0.f, z2 = 0.f, z3 = 0.f;
    #pragma unroll 8
    for (int k = 0; k < din; k++) {
        float wv = Ws[k * 32 + lane];
        z0 = fmaf(hw[k],           wv, z0);
        z1 = fmaf(hw[din + k],     wv, z1);
        z2 = fmaf(hw[2 * din + k], wv, z2);
        z3 = fmaf(hw[3 * din + k], wv, z3);
    }
    float zz[4] = {z0, z1, z2, z3};
    float aS = as[lane], aD = as[32 + lane];
    for (int t = 0; t < cnt; t++) {
        int n = n0 + t;
        g_Zh[n * 32 + lane] = __float2half(zz[t]);
        float ps = zz[t] * aS, pd = zz[t] * aD;
        #pragma unroll
        for (int o = 16; o; o >>= 1) {
            ps += __shfl_down_sync(0xffffffffu, ps, o);
            pd += __shfl_down_sync(0xffffffffu, pd, o);
        }
        if (lane == 0) { g_SS1[n] = ps; g_SD1[n] = pd; }
    }
}

// ===========================================================================
// scan1: per-block exclusive scan of g_deg into g_row, block totals to g_bsum.
// Decoupled finale: LAST finishing block exclusive-scans g_bsum in place,
// patches g_row[N] so row_final(N)==E, and resets g_scan_ctr for next replay.
// ===========================================================================
__global__ void scan1_kernel(int N, int E, int NB)
{
    __shared__ int sh[SCAN_B];
    __shared__ int flagS;
    int tid = threadIdx.x;
    int i = blockIdx.x * SCAN_B + tid;
    int v = (i < N) ? g_deg[i] : 0;
    sh[tid] = v;
    __syncthreads();
    #pragma unroll
    for (int o = 1; o < SCAN_B; o <<= 1) {
        int t = (tid >= o) ? sh[tid - o] : 0;
        __syncthreads();
        sh[tid] += t;
        __syncthreads();
    }
    if (i < N) g_row[i] = sh[tid] - v;          // exclusive within block
    if (tid == SCAN_B - 1) g_bsum[blockIdx.x] = sh[tid];

    __threadfence();
    if (tid == 0) flagS = (atomicAdd(&g_scan_ctr, 1) == gridDim.x - 1);
    __syncthreads();
    if (flagS) {
        int bv = (tid < NB) ? g_bsum[tid] : 0;
        sh[tid] = bv;
        __syncthreads();
        #pragma unroll
        for (int o = 1; o < SCAN_B; o <<= 1) {
            int t = (tid >= o) ? sh[tid - o] : 0;
            __syncthreads();
            sh[tid] += t;
            __syncthreads();
        }
        int excl = sh[tid] - bv;
        if (tid < NB) g_bsum[tid] = excl;       // exclusive block offsets
        if (tid == (N >> 9)) g_row[N] = E - excl;  // row_final(N) == E
        if (tid == 0) g_scan_ctr = 0;           // restore invariant for replay
    }
}

// ===========================================================================
// Scatter with fused offset-apply: slot via decrement of g_deg (which also
// restores g_deg==0 for the next launch). Within-node order is irrelevant
// (sum aggregation).
// ===========================================================================
__global__ void scatter_kernel(const int* __restrict__ src,
                               const int* __restrict__ dst, int E)
{
    int e = blockIdx.x * blockDim.x + threadIdx.x;
    if (e < E) {
        int d = dst[e];
        int c = atomicAdd(&g_deg[d], -1) - 1;           // 0..deg-1, deg -> 0
        int p = g_row[d] + g_bsum[d >> 9] + c;
        g_esrc[p] = src[e];
    }
}

// ===========================================================================
// Gather core: 8 dst nodes per warp, 4 lanes per node, fp16 Z rows (64B/node).
// CSR edge list (L1-friendly: a group's edges are contiguous). Batched esrc:
// the 4 lanes of a group load 4 consecutive esrc (1 line, 1 instr per 4 edges)
// and broadcast via shuffle; loop bound is warp-uniform (cntmax) so shuffles
// are legal, with per-edge predication (masked lanes emit no wavefronts).
// The 4 SS/Z load pairs per batch are independent -> MLP 4.
// ===========================================================================
#define FMA8(W, R)                                                             \
    {                                                                          \
        __half2* hp = (__half2*)&(R);                                          \
        float2 f0 = __half22float2(hp[0]);                                     \
        float2 f1 = __half22float2(hp[1]);                                     \
        float2 f2 = __half22float2(hp[2]);                                     \
        float2 f3 = __half22float2(hp[3]);                                     \
        acc0.x = fmaf(W, f0.x, acc0.x); acc0.y = fmaf(W, f0.y, acc0.y);        \
        acc0.z = fmaf(W, f1.x, acc0.z); acc0.w = fmaf(W, f1.y, acc0.w);        \
        acc1.x = fmaf(W, f2.x, acc1.x); acc1.y = fmaf(W, f2.y, acc1.y);        \
        acc1.z = fmaf(W, f3.x, acc1.z); acc1.w = fmaf(W, f3.y, acc1.w);        \
    }

#define GATHER8_CORE(SScur, SDcur, ZHALF)                                      \
    int lane = threadIdx.x & 31;                                               \
    int l4   = lane & 3;                                                       \
    int gb   = lane & 28;          /* first lane of this 4-lane group */       \
    int warpid = blockIdx.x * (blockDim.x >> 5) + (threadIdx.x >> 5);          \
    int n = warpid * 8 + (lane >> 2);                                          \
    bool valid = (n < N);                                                      \
    int beg = 0, cnt = 0; float sd = 0.f;                                      \
    if (valid) {                                                               \
        beg = g_row[n] + g_bsum[n >> 9];                                       \
        cnt = (g_row[n + 1] + g_bsum[(n + 1) >> 9]) - beg;                     \
        sd  = SDcur[n];                                                        \
    }                                                                          \
    int cntmax = cnt;                                                          \
    cntmax = max(cntmax, __shfl_xor_sync(0xffffffffu, cntmax, 4));             \
    cntmax = max(cntmax, __shfl_xor_sync(0xffffffffu, cntmax, 8));             \
    cntmax = max(cntmax, __shfl_xor_sync(0xffffffffu, cntmax, 16));            \
    const uint4* Zv = (const uint4*)ZHALF;                                     \
    float4 acc0 = make_float4(0.f, 0.f, 0.f, 0.f);                             \
    float4 acc1 = make_float4(0.f, 0.f, 0.f, 0.f);                             \
    float den = 0.f;                                                           \
    for (int base = 0; base < cntmax; base += 4) {                             \
        int myS = 0;                                                           \
        if (base + l4 < cnt) myS = __ldg(g_esrc + beg + base + l4);            \
        _Pragma("unroll")                                                      \
        for (int j = 0; j < 4; j++) {                                          \
            int s = __shfl_sync(0xffffffffu, myS, gb | j);                     \
            if (base + j < cnt) {                                              \
                float x = __ldg(SScur + s) + sd;                               \
                x = (x > 0.f) ? x : 0.01f * x;                                 \
                float w = __expf(x);                                           \
                den += w;                                                      \
                uint4 r = __ldg(Zv + s * 4 + l4);                              \
                FMA8(w, r)                                                     \
            }                                                                  \
        }                                                                      \
    }                                                                          \
    float inv = 1.f / fmaxf(den, 1e-9f);                                       \
    float ha[8];                                                               \
    ha[0] = fmaxf(acc0.x * inv, 0.f); ha[1] = fmaxf(acc0.y * inv, 0.f);        \
    ha[2] = fmaxf(acc0.z * inv, 0.f); ha[3] = fmaxf(acc0.w * inv, 0.f);        \
    ha[4] = fmaxf(acc1.x * inv, 0.f); ha[5] = fmaxf(acc1.y * inv, 0.f);        \
    ha[6] = fmaxf(acc1.z * inv, 0.f); ha[7] = fmaxf(acc1.w * inv, 0.f);
// ha holds relu'd features (8*l4 .. 8*l4+7) of node n.

// ---------------------------------------------------------------------------
// Gather layer 1 + fused layer-2 node GEMM (z2 = h@W2, s_src2, s_dst2).
// ---------------------------------------------------------------------------
__global__ void __launch_bounds__(256)
gather_fuse_L1L2_kernel(int N, const float* __restrict__ W2,
                        const float* __restrict__ a2)
{
    __shared__ float W2s[32 * 32];
    __shared__ float a2s[64];
    int tid0 = threadIdx.x;
    for (int i = tid0; i < 32 * 32; i += blockDim.x) W2s[i] = W2[i];
    if (tid0 < 64) a2s[tid0] = a2[tid0];
    __syncthreads();

    GATHER8_CORE(g_SS1, g_SD1, g_Zh)

    // z2[8 outputs: 8*l4 .. 8*l4+7] = sum_k h[k] * W2[k][outputs]
    const float4* W2v = (const float4*)W2s;    // row k = 8 float4s
    float z2[8];
    #pragma unroll
    for (int j = 0; j < 8; j++) z2[j] = 0.f;
    #pragma unroll
    for (int sl = 0; sl < 4; sl++) {
        #pragma unroll
        for (int i = 0; i < 8; i++) {
            float hk = __shfl_sync(0xffffffffu, ha[i], gb | sl);
            int k = sl * 8 + i;
            float4 wA = W2v[k * 8 + 2 * l4];
            float4 wB = W2v[k * 8 + 2 * l4 + 1];
            z2[0] = fmaf(hk, wA.x, z2[0]); z2[1] = fmaf(hk, wA.y, z2[1]);
            z2[2] = fmaf(hk, wA.z, z2[2]); z2[3] = fmaf(hk, wA.w, z2[3]);
            z2[4] = fmaf(hk, wB.x, z2[4]); z2[5] = fmaf(hk, wB.y, z2[5]);
            z2[6] = fmaf(hk, wB.z, z2[6]); z2[7] = fmaf(hk, wB.w, z2[7]);
        }
    }
    float ps = 0.f, pd = 0.f;
    #pragma unroll
    for (int j = 0; j < 8; j++) {
        ps = fmaf(z2[j], a2s[8 * l4 + j], ps);
        pd = fmaf(z2[j], a2s[32 + 8 * l4 + j], pd);
    }
    ps += __shfl_xor_sync(0xffffffffu, ps, 1);
    ps += __shfl_xor_sync(0xffffffffu, ps, 2);
    pd += __shfl_xor_sync(0xffffffffu, pd, 1);
    pd += __shfl_xor_sync(0xffffffffu, pd, 2);
    if (valid) {
        __half2 p0 = __floats2half2_rn(z2[0], z2[1]);
        __half2 p1 = __floats2half2_rn(z2[2], z2[3]);
        __half2 p2 = __floats2half2_rn(z2[4], z2[5]);
        __half2 p3 = __floats2half2_rn(z2[6], z2[7]);
        uint4 raw;
        raw.x = *reinterpret_cast<unsigned int*>(&p0);
        raw.y = *reinterpret_cast<unsigned int*>(&p1);
        raw.z = *reinterpret_cast<unsigned int*>(&p2);
        raw.w = *reinterpret_cast<unsigned int*>(&p3);
        ((uint4*)g_Z2h)[n * 4 + l4] = raw;
        if (l4 == 0) { g_SS2[n] = ps; g_SD2[n] = pd; }
    }
}

// ---------------------------------------------------------------------------
// Gather layer 2 + fused layer-3 node GEMM (scalar z3 = h.W3, s3 scalars).
// ---------------------------------------------------------------------------
__global__ void __launch_bounds__(256)
gather_fuse_L2L3_kernel(int N, const float* __restrict__ W3,
                        const float* __restrict__ a3)
{
    __shared__ float W3s[32];
    __shared__ float a3s[2];
    int tid0 = threadIdx.x;
    if (tid0 < 32) W3s[tid0] = W3[tid0];
    if (tid0 < 2)  a3s[tid0] = a3[tid0];
    __syncthreads();

    GATHER8_CORE(g_SS2, g_SD2, g_Z2h)

    float z3 = 0.f;
    #pragma unroll
    for (int i = 0; i < 8; i++) z3 = fmaf(ha[i], W3s[8 * l4 + i], z3);
    z3 += __shfl_xor_sync(0xffffffffu, z3, 1);
    z3 += __shfl_xor_sync(0xffffffffu, z3, 2);
    if (valid && l4 == 0) {
        g_Zs[n]  = z3;
        g_SS3[n] = z3 * a3s[0];
        g_SD3[n] = z3 * a3s[1];
    }
}

// ---------------------------------------------------------------------------
// Final gather (dout=1): 8 nodes/warp, 4 lanes split each node's edges
// (esrc reads naturally coalesced per group), normalize + sigmoid -> output.
// ---------------------------------------------------------------------------
__global__ void __launch_bounds__(256)
gather1_kernel(int N, float* __restrict__ out)
{
    int lane = threadIdx.x & 31;
    int l4   = lane & 3;
    int warpid = blockIdx.x * (blockDim.x >> 5) + (threadIdx.x >> 5);
    int n = warpid * 8 + (lane >> 2);
    bool valid = (n < N);
    int beg = 0, end = 0; float sd = 0.f;
    if (valid) {
        beg = g_row[n] + g_bsum[n >> 9];
        end = g_row[n + 1] + g_bsum[(n + 1) >> 9];
        sd  = g_SD3[n];
    }

    float acc = 0.f, den = 0.f;
    for (int i = beg + l4; i < end; i += 4) {
        int s = __ldg(g_esrc + i);
        float x = __ldg(g_SS3 + s) + sd;
        x = (x > 0.f) ? x : 0.01f * x;
        float w = __expf(x);
        den += w;
        acc = fmaf(w, __ldg(g_Zs + s), acc);
    }
    den += __shfl_xor_sync(0xffffffffu, den, 1);
    den += __shfl_xor_sync(0xffffffffu, den, 2);
    acc += __shfl_xor_sync(0xffffffffu, acc, 1);
    acc += __shfl_xor_sync(0xffffffffu, acc, 2);
    if (valid && l4 == 0) {
        float v = acc / fmaxf(den, 1e-9f);
        out[n] = 1.f / (1.f + __expf(-v));
    }
}

// ===========================================================================
extern "C" void kernel_launch(void* const* d_in, const int* in_sizes, int n_in,
                              void* d_out, int out_size)
{
    const float* feat = (const float*)d_in[0];
    const int*   src  = (const int*)d_in[1];
    const int*   dst  = (const int*)d_in[2];
    const float* W1   = (const float*)d_in[3];
    const float* a1   = (const float*)d_in[4];
    const float* W2   = (const float*)d_in[5];
    const float* a2   = (const float*)d_in[6];
    const float* W3   = (const float*)d_in[7];
    const float* a3   = (const float*)d_in[8];

    const int E    = in_sizes[1];
    const int d1   = in_sizes[4] / 2;          // 32
    const int din1 = in_sizes[3] / d1;         // 128
    const int N    = in_sizes[0] / din1;       // 100000

    const int NT  = 256;
    const int WPB = NT / 32;                   // 8 warps/block
    float* out = (float*)d_out;

    // ---- fused dst-histogram + layer-1 node GEMM ----
    const int histBlocks = (E + NT - 1) / NT;
    const int gemmBlocks = (N + 4 * WPB - 1) / (4 * WPB);   // 4 nodes/warp
    {
        size_t shm = (size_t)(din1 * 32 + 64 + WPB * 4 * din1) * sizeof(float);
        hist_gemm_kernel<<<histBlocks + gemmBlocks, NT, shm>>>(
            dst, E, histBlocks, feat, W1, a1, N, din1);
    }

    // ---- CSR scan (decoupled, single kernel) + scatter (fused apply) ----
    const int NB = (N + SCAN_B - 1) / SCAN_B;
    scan1_kernel<<<NB, SCAN_B>>>(N, E, NB);
    scatter_kernel<<<histBlocks, NT>>>(src, dst, E);

    // ---- Gather chains (8 nodes/warp, 4 lanes/node, fp16 Z, batched esrc) ----
    const int octs = (N + 7) / 8;
    const int gBlocks = (octs + WPB - 1) / WPB;
    gather_fuse_L1L2_kernel<<<gBlocks, NT>>>(N, W2, a2);
    gather_fuse_L2L3_kernel<<<gBlocks, NT>>>(N, W3, a3);
    gather1_kernel<<<gBlocks, NT>>>(N, out);
}

// round 16
// speedup vs baseline: 1.0735x; 1.0006x over previous
#include <cuda_runtime.h>
#include <cuda_fp16.h>

// Problem-fixed maxima (from setup_inputs): N=100000, E=1600000, dims 128->32->32->1.
#define MAXN 100000
#define MAXE 1600000
#define SCAN_B 512
#define MAXNB ((MAXN + SCAN_B - 1) / SCAN_B)   // 196

// ---- scratch (device globals; allocation-free per harness rules) ----
// Zero-initialized at module load; every launch restores g_deg==0 and
// g_scan_ctr==0 (scatter decrements deg back to 0; scan1 last block resets ctr),
// so graph replays see identical initial state.
__device__ __half g_Zh[MAXN * 32];   // layer-1 z (fp16 for gather bandwidth)
__device__ __half g_Z2h[MAXN * 32];  // layer-2 z (fp16)
__device__ float g_Zs[MAXN];         // layer-3 z (scalar, fp32)
__device__ float g_SS1[MAXN], g_SD1[MAXN];
__device__ float g_SS2[MAXN], g_SD2[MAXN];
__device__ float g_SS3[MAXN], g_SD3[MAXN];
__device__ int   g_deg[MAXN];        // degree counters (return to 0 each launch)
__device__ int   g_row[MAXN + 1];    // block-local exclusive scan of deg
__device__ int   g_bsum[MAXNB];      // exclusive-scanned block sums
__device__ int2  g_ew[MAXE];         // dst-sorted (src, w1-bits) pairs
__device__ int   g_scan_ctr;         // decoupled-scan counter (self-resetting)

// row_final(i) = g_row[i] + g_bsum[i >> 9]  (valid for 0..N; g_row[N] patched)

// ===========================================================================
// Fused: dst histogram (blocks [0, histBlocks)) + layer-1 node GEMM
// (blocks [histBlocks, ...)). Independent work co-scheduled on the chip.
// GEMM: z = feat@W1 (stored fp16), s_src1/s_dst1. dout=32, 4 nodes per warp.
// ===========================================================================
__global__ void __launch_bounds__(256)
hist_gemm_kernel(const int* __restrict__ dst, int E, int histBlocks,
                 const float* __restrict__ feat,
                 const float* __restrict__ W,
                 const float* __restrict__ a,
                 int N, int din)
{
    if (blockIdx.x < histBlocks) {
        int e = blockIdx.x * blockDim.x + threadIdx.x;
        if (e < E) atomicAdd(&g_deg[dst[e]], 1);
        return;
    }
    int bid = blockIdx.x - histBlocks;

    extern __shared__ float sh[];
    float* Ws = sh;                // din*32
    float* as = Ws + din * 32;     // 64
    float* hs = as + 64;           // WPB * 4 * din

    int tid = threadIdx.x;
    for (int i = tid; i < din * 32; i += blockDim.x) Ws[i] = W[i];
    for (int i = tid; i < 64; i += blockDim.x) as[i] = a[i];
    __syncthreads();

    int lane = tid & 31;
    int wrp  = tid >> 5;
    int WPB  = blockDim.x >> 5;
    float* hw = hs + wrp * 4 * din;

    int n0 = (bid * WPB + wrp) * 4;
    if (n0 >= N) return;
    int cnt = (N - n0 < 4) ? (N - n0) : 4;

    for (int t = 0; t < cnt; t++) {
        const float* hr = feat + (long long)(n0 + t) * din;
        for (int k = lane; k < din; k += 32) hw[t * din + k] = hr[k];
    }
    for (int t = cnt; t < 4; t++)
        for (int k = lane; k < din; k += 32) hw[t * din + k] = 0.f;
    __syncwarp();

    float z0 = 0.f, z1 = 0.f, z2 = 0.f, z3 = 0.f;
    #pragma unroll 8
    for (int k = 0; k < din; k++) {
        float wv = Ws[k * 32 + lane];
        z0 = fmaf(hw[k],           wv, z0);
        z1 = fmaf(hw[din + k],     wv, z1);
        z2 = fmaf(hw[2 * din + k], wv, z2);
        z3 = fmaf(hw[3 * din + k], wv, z3);
    }
    float zz[4] = {z0, z1, z2, z3};
    float aS = as[lane], aD = as[32 + lane];
    for (int t = 0; t < cnt; t++) {
        int n = n0 + t;
        g_Zh[n * 32 + lane] = __float2half(zz[t]);
        float ps = zz[t] * aS, pd = zz[t] * aD;
        #pragma unroll
        for (int o = 16; o; o >>= 1) {
            ps += __shfl_down_sync(0xffffffffu, ps, o);
            pd += __shfl_down_sync(0xffffffffu, pd, o);
        }
        if (lane == 0) { g_SS1[n] = ps; g_SD1[n] = pd; }
    }
}

// ===========================================================================
// scan1: per-block exclusive scan of g_deg into g_row, block totals to g_bsum.
// Decoupled finale: LAST finishing block exclusive-scans g_bsum in place,
// patches g_row[N] so row_final(N)==E, and resets g_scan_ctr for next replay.
// ===========================================================================
__global__ void scan1_kernel(int N, int E, int NB)
{
    __shared__ int sh[SCAN_B];
    __shared__ int flagS;
    int tid = threadIdx.x;
    int i = blockIdx.x * SCAN_B + tid;
    int v = (i < N) ? g_deg[i] : 0;
    sh[tid] = v;
    __syncthreads();
    #pragma unroll
    for (int o = 1; o < SCAN_B; o <<= 1) {
        int t = (tid >= o) ? sh[tid - o] : 0;
        __syncthreads();
        sh[tid] += t;
        __syncthreads();
    }
    if (i < N) g_row[i] = sh[tid] - v;          // exclusive within block
    if (tid == SCAN_B - 1) g_bsum[blockIdx.x] = sh[tid];

    __threadfence();
    if (tid == 0) flagS = (atomicAdd(&g_scan_ctr, 1) == gridDim.x - 1);
    __syncthreads();
    if (flagS) {
        int bv = (tid < NB) ? g_bsum[tid] : 0;
        sh[tid] = bv;
        __syncthreads();
        #pragma unroll
        for (int o = 1; o < SCAN_B; o <<= 1) {
            int t = (tid >= o) ? sh[tid - o] : 0;
            __syncthreads();
            sh[tid] += t;
            __syncthreads();
        }
        int excl = sh[tid] - bv;
        if (tid < NB) g_bsum[tid] = excl;       // exclusive block offsets
        if (tid == (N >> 9)) g_row[N] = E - excl;  // row_final(N) == E
        if (tid == 0) g_scan_ctr = 0;           // restore invariant for replay
    }
}

// ===========================================================================
// Scatter with fused offset-apply AND layer-1 edge-weight precompute.
// Slot via decrement of g_deg (restores g_deg==0 for replay). Stores the
// (src, w1) pair so the L1 gather needs no SS load and no expf.
// SS1/SD1 are ready (hist_gemm ran before). Within-node order irrelevant
// for correctness, and w values are identical to computing them in-gather.
// ===========================================================================
__global__ void scatter_kernel(const int* __restrict__ src,
                               const int* __restrict__ dst, int E)
{
    int e = blockIdx.x * blockDim.x + threadIdx.x;
    if (e < E) {
        int d = dst[e];
        int s = src[e];
        int c = atomicAdd(&g_deg[d], -1) - 1;           // 0..deg-1, deg -> 0
        int p = g_row[d] + g_bsum[d >> 9] + c;
        float x = __ldg(g_SS1 + s) + __ldg(g_SD1 + d);
        x = (x > 0.f) ? x : 0.01f * x;                  // leaky_relu
        float w = __expf(x);
        g_ew[p] = make_int2(s, __float_as_int(w));
    }
}

// ===========================================================================
// Gather cores: 8 dst nodes per warp, 4 lanes per node, fp16 Z rows (64B/node),
// CSR layout, per-group divergent loop (R12 structure — proven fastest).
// All 4 lanes of a group read the SAME edge record (broadcast, 1 wavefront),
// each lane loads its 16B quarter of the Z row (1 wavefront).
// ===========================================================================
#define FMA8(W, R)                                                             \
    {                                                                          \
        __half2* hp = (__half2*)&(R);                                          \
        float2 f0 = __half22float2(hp[0]);                                     \
        float2 f1 = __half22float2(hp[1]);                                     \
        float2 f2 = __half22float2(hp[2]);                                     \
        float2 f3 = __half22float2(hp[3]);                                     \
        acc0.x = fmaf(W, f0.x, acc0.x); acc0.y = fmaf(W, f0.y, acc0.y);        \
        acc0.z = fmaf(W, f1.x, acc0.z); acc0.w = fmaf(W, f1.y, acc0.w);        \
        acc1.x = fmaf(W, f2.x, acc1.x); acc1.y = fmaf(W, f2.y, acc1.y);        \
        acc1.z = fmaf(W, f3.x, acc1.z); acc1.w = fmaf(W, f3.y, acc1.w);        \
    }

#define GATHER8_PROLOGUE                                                       \
    int lane = threadIdx.x & 31;                                               \
    int l4   = lane & 3;                                                       \
    int gb   = lane & 28;                                                      \
    int warpid = blockIdx.x * (blockDim.x >> 5) + (threadIdx.x >> 5);          \
    int n = warpid * 8 + (lane >> 2);                                          \
    bool valid = (n < N);                                                      \
    int beg = 0, cnt = 0;                                                      \
    if (valid) {                                                               \
        beg = g_row[n] + g_bsum[n >> 9];                                       \
        cnt = (g_row[n + 1] + g_bsum[(n + 1) >> 9]) - beg;                     \
    }                                                                          \
    float4 acc0 = make_float4(0.f, 0.f, 0.f, 0.f);                             \
    float4 acc1 = make_float4(0.f, 0.f, 0.f, 0.f);                             \
    float den = 0.f;

#define GATHER8_EPILOGUE                                                       \
    float inv = 1.f / fmaxf(den, 1e-9f);                                       \
    float ha[8];                                                               \
    ha[0] = fmaxf(acc0.x * inv, 0.f); ha[1] = fmaxf(acc0.y * inv, 0.f);        \
    ha[2] = fmaxf(acc0.z * inv, 0.f); ha[3] = fmaxf(acc0.w * inv, 0.f);        \
    ha[4] = fmaxf(acc1.x * inv, 0.f); ha[5] = fmaxf(acc1.y * inv, 0.f);        \
    ha[6] = fmaxf(acc1.z * inv, 0.f); ha[7] = fmaxf(acc1.w * inv, 0.f);

// Layer-1 variant: w preloaded in the edge record. 2 wavefronts/edge.
#define GATHER8_PRE(ZHALF)                                                     \
    GATHER8_PROLOGUE                                                           \
    const uint4* Zv = (const uint4*)ZHALF;                                     \
    {                                                                          \
        int t = 0;                                                             \
        for (; t + 2 <= cnt; t += 2) {                                         \
            int2 e0 = __ldg(g_ew + beg + t);                                   \
            int2 e1 = __ldg(g_ew + beg + t + 1);                               \
            float w0 = __int_as_float(e0.y);                                   \
            float w1 = __int_as_float(e1.y);                                   \
            uint4 r0 = __ldg(Zv + e0.x * 4 + l4);                              \
            uint4 r1 = __ldg(Zv + e1.x * 4 + l4);                              \
            den += w0 + w1;                                                    \
            FMA8(w0, r0)                                                       \
            FMA8(w1, r1)                                                       \
        }                                                                      \
        if (t < cnt) {                                                         \
            int2 e0 = __ldg(g_ew + beg + t);                                   \
            float w0 = __int_as_float(e0.y);                                   \
            uint4 r0 = __ldg(Zv + e0.x * 4 + l4);                              \
            den += w0;                                                         \
            FMA8(w0, r0)                                                       \
        }                                                                      \
    }                                                                          \
    GATHER8_EPILOGUE

// Generic variant: w computed from SS/SD (layers 2+). 3 wavefronts/edge.
#define GATHER8_CORE(SScur, SDcur, ZHALF)                                      \
    GATHER8_PROLOGUE                                                           \
    float sd = valid ? SDcur[n] : 0.f;                                         \
    const uint4* Zv = (const uint4*)ZHALF;                                     \
    {                                                                          \
        int t = 0;                                                             \
        for (; t + 2 <= cnt; t += 2) {                                         \
            int s0 = __ldg(g_ew + beg + t)->x;                                 \
            int s1 = __ldg(g_ew + beg + t + 1)->x;                             \
            float x0 = __ldg(SScur + s0) + sd;                                 \
            float x1 = __ldg(SScur + s1) + sd;                                 \
            uint4 r0 = __ldg(Zv + s0 * 4 + l4);                                \
            uint4 r1 = __ldg(Zv + s1 * 4 + l4);                                \
            x0 = (x0 > 0.f) ? x0 : 0.01f * x0;                                 \
            x1 = (x1 > 0.f) ? x1 : 0.01f * x1;                                 \
            float w0 = __expf(x0);                                             \
            float w1 = __expf(x1);                                             \
            den += w0 + w1;                                                    \
            FMA8(w0, r0)                                                       \
            FMA8(w1, r1)                                                       \
        }                                                                      \
        if (t < cnt) {                                                         \
            int s0 = __ldg(g_ew + beg + t)->x;                                 \
            float x0 = __ldg(SScur + s0) + sd;                                 \
            uint4 r0 = __ldg(Zv + s0 * 4 + l4);                                \
            x0 = (x0 > 0.f) ? x0 : 0.01f * x0;                                 \
            float w0 = __expf(x0);                                             \
            den += w0;                                                         \
            FMA8(w0, r0)                                                       \
        }                                                                      \
    }                                                                          \
    GATHER8_EPILOGUE

// helper: __ldg on int2 pointer returning pointer-like access
__device__ __forceinline__ const int2* ldg_ew_ptr(const int2* p) { return p; }

// ---------------------------------------------------------------------------
// Gather layer 1 (precomputed w) + fused layer-2 node GEMM.
// ---------------------------------------------------------------------------
__global__ void __launch_bounds__(256)
gather_fuse_L1L2_kernel(int N, const float* __restrict__ W2,
                        const float* __restrict__ a2)
{
    __shared__ float W2s[32 * 32];
    __shared__ float a2s[64];
    int tid0 = threadIdx.x;
    for (int i = tid0; i < 32 * 32; i += blockDim.x) W2s[i] = W2[i];
    if (tid0 < 64) a2s[tid0] = a2[tid0];
    __syncthreads();

    GATHER8_PRE(g_Zh)

    // z2[8 outputs: 8*l4 .. 8*l4+7] = sum_k h[k] * W2[k][outputs]
    const float4* W2v = (const float4*)W2s;    // row k = 8 float4s
    float z2[8];
    #pragma unroll
    for (int j = 0; j < 8; j++) z2[j] = 0.f;
    #pragma unroll
    for (int sl = 0; sl < 4; sl++) {
        #pragma unroll
        for (int i = 0; i < 8; i++) {
            float hk = __shfl_sync(0xffffffffu, ha[i], gb | sl);
            int k = sl * 8 + i;
            float4 wA = W2v[k * 8 + 2 * l4];
            float4 wB = W2v[k * 8 + 2 * l4 + 1];
            z2[0] = fmaf(hk, wA.x, z2[0]); z2[1] = fmaf(hk, wA.y, z2[1]);
            z2[2] = fmaf(hk, wA.z, z2[2]); z2[3] = fmaf(hk, wA.w, z2[3]);
            z2[4] = fmaf(hk, wB.x, z2[4]); z2[5] = fmaf(hk, wB.y, z2[5]);
            z2[6] = fmaf(hk, wB.z, z2[6]); z2[7] = fmaf(hk, wB.w, z2[7]);
        }
    }
    float ps = 0.f, pd = 0.f;
    #pragma unroll
    for (int j = 0; j < 8; j++) {
        ps = fmaf(z2[j], a2s[8 * l4 + j], ps);
        pd = fmaf(z2[j], a2s[32 + 8 * l4 + j], pd);
    }
    ps += __shfl_xor_sync(0xffffffffu, ps, 1);
    ps += __shfl_xor_sync(0xffffffffu, ps, 2);
    pd += __shfl_xor_sync(0xffffffffu, pd, 1);
    pd += __shfl_xor_sync(0xffffffffu, pd, 2);
    if (valid) {
        __half2 p0 = __floats2half2_rn(z2[0], z2[1]);
        __half2 p1 = __floats2half2_rn(z2[2], z2[3]);
        __half2 p2 = __floats2half2_rn(z2[4], z2[5]);
        __half2 p3 = __floats2half2_rn(z2[6], z2[7]);
        uint4 raw;
        raw.x = *reinterpret_cast<unsigned int*>(&p0);
        raw.y = *reinterpret_cast<unsigned int*>(&p1);
        raw.z = *reinterpret_cast<unsigned int*>(&p2);
        raw.w = *reinterpret_cast<unsigned int*>(&p3);
        ((uint4*)g_Z2h)[n * 4 + l4] = raw;
        if (l4 == 0) { g_SS2[n] = ps; g_SD2[n] = pd; }
    }
}

// ---------------------------------------------------------------------------
// Gather layer 2 (computed w) + fused layer-3 node GEMM.
// ---------------------------------------------------------------------------
__global__ void __launch_bounds__(256)
gather_fuse_L2L3_kernel(int N, const float* __restrict__ W3,
                        const float* __restrict__ a3)
{
    __shared__ float W3s[32];
    __shared__ float a3s[2];
    int tid0 = threadIdx.x;
    if (tid0 < 32) W3s[tid0] = W3[tid0];
    if (tid0 < 2)  a3s[tid0] = a3[tid0];
    __syncthreads();

    GATHER8_PROLOGUE
    float sd = valid ? g_SD2[n] : 0.f;
    const uint4* Zv = (const uint4*)g_Z2h;
    {
        int t = 0;
        for (; t + 2 <= cnt; t += 2) {
            int s0 = __ldg(&g_ew[beg + t].x);
            int s1 = __ldg(&g_ew[beg + t + 1].x);
            float x0 = __ldg(g_SS2 + s0) + sd;
            float x1 = __ldg(g_SS2 + s1) + sd;
            uint4 r0 = __ldg(Zv + s0 * 4 + l4);
            uint4 r1 = __ldg(Zv + s1 * 4 + l4);
            x0 = (x0 > 0.f) ? x0 : 0.01f * x0;
            x1 = (x1 > 0.f) ? x1 : 0.01f * x1;
            float w0 = __expf(x0);
            float w1 = __expf(x1);
            den += w0 + w1;
            FMA8(w0, r0)
            FMA8(w1, r1)
        }
        if (t < cnt) {
            int s0 = __ldg(&g_ew[beg + t].x);
            float x0 = __ldg(g_SS2 + s0) + sd;
            uint4 r0 = __ldg(Zv + s0 * 4 + l4);
            x0 = (x0 > 0.f) ? x0 : 0.01f * x0;
            float w0 = __expf(x0);
            den += w0;
            FMA8(w0, r0)
        }
    }
    GATHER8_EPILOGUE
    (void)gb;

    float z3 = 0.f;
    #pragma unroll
    for (int i = 0; i < 8; i++) z3 = fmaf(ha[i], W3s[8 * l4 + i], z3);
    z3 += __shfl_xor_sync(0xffffffffu, z3, 1);
    z3 += __shfl_xor_sync(0xffffffffu, z3, 2);
    if (valid && l4 == 0) {
        g_Zs[n]  = z3;
        g_SS3[n] = z3 * a3s[0];
        g_SD3[n] = z3 * a3s[1];
    }
}

// ---------------------------------------------------------------------------
// Final gather (dout=1): 8 nodes/warp, 4 lanes split each node's edges,
// normalize + sigmoid -> output.
// ---------------------------------------------------------------------------
__global__ void __launch_bounds__(256)
gather1_kernel(int N, float* __restrict__ out)
{
    int lane = threadIdx.x & 31;
    int l4   = lane & 3;
    int warpid = blockIdx.x * (blockDim.x >> 5) + (threadIdx.x >> 5);
    int n = warpid * 8 + (lane >> 2);
    bool valid = (n < N);
    int beg = 0, end = 0; float sd = 0.f;
    if (valid) {
        beg = g_row[n] + g_bsum[n >> 9];
        end = g_row[n + 1] + g_bsum[(n + 1) >> 9];
        sd  = g_SD3[n];
    }

    float acc = 0.f, den = 0.f;
    for (int i = beg + l4; i < end; i += 4) {
        int s = __ldg(&g_ew[i].x);
        float x = __ldg(g_SS3 + s) + sd;
        x = (x > 0.f) ? x : 0.01f * x;
        float w = __expf(x);
        den += w;
        acc = fmaf(w, __ldg(g_Zs + s), acc);
    }
    den += __shfl_xor_sync(0xffffffffu, den, 1);
    den += __shfl_xor_sync(0xffffffffu, den, 2);
    acc += __shfl_xor_sync(0xffffffffu, acc, 1);
    acc += __shfl_xor_sync(0xffffffffu, acc, 2);
    if (valid && l4 == 0) {
        float v = acc / fmaxf(den, 1e-9f);
        out[n] = 1.f / (1.f + __expf(-v));
    }
}

// ===========================================================================
extern "C" void kernel_launch(void* const* d_in, const int* in_sizes, int n_in,
                              void* d_out, int out_size)
{
    const float* feat = (const float*)d_in[0];
    const int*   src  = (const int*)d_in[1];
    const int*   dst  = (const int*)d_in[2];
    const float* W1   = (const float*)d_in[3];
    const float* a1   = (const float*)d_in[4];
    const float* W2   = (const float*)d_in[5];
    const float* a2   = (const float*)d_in[6];
    const float* W3   = (const float*)d_in[7];
    const float* a3   = (const float*)d_in[8];

    const int E    = in_sizes[1];
    const int d1   = in_sizes[4] / 2;          // 32
    const int din1 = in_sizes[3] / d1;         // 128
    const int N    = in_sizes[0] / din1;       // 100000

    const int NT  = 256;
    const int WPB = NT / 32;                   // 8 warps/block
    float* out = (float*)d_out;

    // ---- fused dst-histogram + layer-1 node GEMM ----
    const int histBlocks = (E + NT - 1) / NT;
    const int gemmBlocks = (N + 4 * WPB - 1) / (4 * WPB);   // 4 nodes/warp
    {
        size_t shm = (size_t)(din1 * 32 + 64 + WPB * 4 * din1) * sizeof(float);
        hist_gemm_kernel<<<histBlocks + gemmBlocks, NT, shm>>>(
            dst, E, histBlocks, feat, W1, a1, N, din1);
    }

    // ---- CSR scan (decoupled) + scatter (fused apply + w1 precompute) ----
    const int NB = (N + SCAN_B - 1) / SCAN_B;
    scan1_kernel<<<NB, SCAN_B>>>(N, E, NB);
    scatter_kernel<<<histBlocks, NT>>>(src, dst, E);

    // ---- Gather chains (8 nodes/warp, 4 lanes/node, fp16 Z, CSR) ----
    const int octs = (N + 7) / 8;
    const int gBlocks = (octs + WPB - 1) / WPB;
    gather_fuse_L1L2_kernel<<<gBlocks, NT>>>(N, W2, a2);
    gather_fuse_L2L3_kernel<<<gBlocks, NT>>>(N, W3, a3);
    gather1_kernel<<<gBlocks, NT>>>(N, out);
}

// round 17
// speedup vs baseline: 1.1530x; 1.0740x over previous
#include <cuda_runtime.h>
#include <cuda_fp16.h>

// Problem-fixed maxima (from setup_inputs): N=100000, E=1600000, dims 128->32->32->1.
#define MAXN 100000
#define MAXE 1600000
#define SCAN_B 512
#define MAXNB ((MAXN + SCAN_B - 1) / SCAN_B)   // 196

// ---- scratch (device globals; allocation-free per harness rules) ----
// Zero-initialized at module load; every launch restores g_deg==0 and
// g_scan_ctr==0 (scatter decrements deg back to 0; scan1 last block resets ctr),
// so graph replays see identical initial state.
__device__ __half g_Zh[MAXN * 32];   // layer-1 z (fp16 for gather bandwidth)
__device__ __half g_Z2h[MAXN * 32];  // layer-2 z (fp16)
__device__ float g_Zs[MAXN];         // layer-3 z (scalar, fp32)
__device__ float g_SS1[MAXN], g_SD1[MAXN];
__device__ float g_SS2[MAXN], g_SD2[MAXN];
__device__ float g_SS3[MAXN], g_SD3[MAXN];
__device__ int   g_deg[MAXN];        // degree counters (return to 0 each launch)
__device__ int   g_row[MAXN + 1];    // block-local exclusive scan of deg
__device__ int   g_bsum[MAXNB];      // exclusive-scanned block sums
__device__ int   g_esrc[MAXE];       // dst-sorted src ids (CSR order, 4B records)
__device__ int   g_scan_ctr;         // decoupled-scan counter (self-resetting)

// row_final(i) = g_row[i] + g_bsum[i >> 9]  (valid for 0..N; g_row[N] patched)

// ===========================================================================
// Fused: dst histogram (blocks [0, histBlocks)) + layer-1 node GEMM
// (blocks [histBlocks, ...)). Independent work co-scheduled on the chip.
// GEMM: z = feat@W1 (stored fp16), s_src1/s_dst1. dout=32, 4 nodes per warp.
// ===========================================================================
__global__ void __launch_bounds__(256)
hist_gemm_kernel(const int* __restrict__ dst, int E, int histBlocks,
                 const float* __restrict__ feat,
                 const float* __restrict__ W,
                 const float* __restrict__ a,
                 int N, int din)
{
    if (blockIdx.x < histBlocks) {
        int e = blockIdx.x * blockDim.x + threadIdx.x;
        if (e < E) atomicAdd(&g_deg[dst[e]], 1);
        return;
    }
    int bid = blockIdx.x - histBlocks;

    extern __shared__ float sh[];
    float* Ws = sh;                // din*32
    float* as = Ws + din * 32;     // 64
    float* hs = as + 64;           // WPB * 4 * din

    int tid = threadIdx.x;
    for (int i = tid; i < din * 32; i += blockDim.x) Ws[i] = W[i];
    for (int i = tid; i < 64; i += blockDim.x) as[i] = a[i];
    __syncthreads();

    int lane = tid & 31;
    int wrp  = tid >> 5;
    int WPB  = blockDim.x >> 5;
    float* hw = hs + wrp * 4 * din;

    int n0 = (bid * WPB + wrp) * 4;
    if (n0 >= N) return;
    int cnt = (N - n0 < 4) ? (N - n0) : 4;

    for (int t = 0; t < cnt; t++) {
        const float* hr = feat + (long long)(n0 + t) * din;
        for (int k = lane; k < din; k += 32) hw[t * din + k] = hr[k];
    }
    for (int t = cnt; t < 4; t++)
        for (int k = lane; k < din; k += 32) hw[t * din + k] = 0.f;
    __syncwarp();

    float z0 = 0.f, z1 = 0.f, z2 = 0.f, z3 = 0.f;
    #pragma unroll 8
    for (int k = 0; k < din; k++) {
        float wv = Ws[k * 32 + lane];
        z0 = fmaf(hw[k],           wv, z0);
        z1 = fmaf(hw[din + k],     wv, z1);
        z2 = fmaf(hw[2 * din + k], wv, z2);
        z3 = fmaf(hw[3 * din + k], wv, z3);
    }
    float zz[4] = {z0, z1, z2, z3};
    float aS = as[lane], aD = as[32 + lane];
    for (int t = 0; t < cnt; t++) {
        int n = n0 + t;
        g_Zh[n * 32 + lane] = __float2half(zz[t]);
        float ps = zz[t] * aS, pd = zz[t] * aD;
        #pragma unroll
        for (int o = 16; o; o >>= 1) {
            ps += __shfl_down_sync(0xffffffffu, ps, o);
            pd += __shfl_down_sync(0xffffffffu, pd, o);
        }
        if (lane == 0) { g_SS1[n] = ps; g_SD1[n] = pd; }
    }
}

// ===========================================================================
// scan1: per-block exclusive scan of g_deg into g_row, block totals to g_bsum.
// Decoupled finale: LAST finishing block exclusive-scans g_bsum in place,
// patches g_row[N] so row_final(N)==E, and resets g_scan_ctr for next replay.
// ===========================================================================
__global__ void scan1_kernel(int N, int E, int NB)
{
    __shared__ int sh[SCAN_B];
    __shared__ int flagS;
    int tid = threadIdx.x;
    int i = blockIdx.x * SCAN_B + tid;
    int v = (i < N) ? g_deg[i] : 0;
    sh[tid] = v;
    __syncthreads();
    #pragma unroll
    for (int o = 1; o < SCAN_B; o <<= 1) {
        int t = (tid >= o) ? sh[tid - o] : 0;
        __syncthreads();
        sh[tid] += t;
        __syncthreads();
    }
    if (i < N) g_row[i] = sh[tid] - v;          // exclusive within block
    if (tid == SCAN_B - 1) g_bsum[blockIdx.x] = sh[tid];

    __threadfence();
    if (tid == 0) flagS = (atomicAdd(&g_scan_ctr, 1) == gridDim.x - 1);
    __syncthreads();
    if (flagS) {
        int bv = (tid < NB) ? g_bsum[tid] : 0;
        sh[tid] = bv;
        __syncthreads();
        #pragma unroll
        for (int o = 1; o < SCAN_B; o <<= 1) {
            int t = (tid >= o) ? sh[tid - o] : 0;
            __syncthreads();
            sh[tid] += t;
            __syncthreads();
        }
        int excl = sh[tid] - bv;
        if (tid < NB) g_bsum[tid] = excl;       // exclusive block offsets
        if (tid == (N >> 9)) g_row[N] = E - excl;  // row_final(N) == E
        if (tid == 0) g_scan_ctr = 0;           // restore invariant for replay
    }
}

// ===========================================================================
// Scatter with fused offset-apply: slot via decrement of g_deg (which also
// restores g_deg==0 for the next launch). Within-node order is irrelevant
// (sum aggregation).
// ===========================================================================
__global__ void scatter_kernel(const int* __restrict__ src,
                               const int* __restrict__ dst, int E)
{
    int e = blockIdx.x * blockDim.x + threadIdx.x;
    if (e < E) {
        int d = dst[e];
        int c = atomicAdd(&g_deg[d], -1) - 1;           // 0..deg-1, deg -> 0
        int p = g_row[d] + g_bsum[d >> 9] + c;
        g_esrc[p] = src[e];
    }
}

// ===========================================================================
// Gather core: 8 dst nodes per warp, 4 lanes per node, fp16 Z rows (64B/node),
// CSR layout, per-group divergent loop (R12 structure — proven fastest).
// All 4 lanes of a group read the SAME esrc/SS (broadcast, 1 wavefront each),
// each lane loads its 16B quarter of the Z row. 4-deep unroll -> 4 independent
// esrc->SS->Z chains in flight per warp (MLP 4) to hide the ~234cyc L2 hit.
// ===========================================================================
#define FMA8(W, R)                                                             \
    {                                                                          \
        __half2* hp = (__half2*)&(R);                                          \
        float2 f0 = __half22float2(hp[0]);                                     \
        float2 f1 = __half22float2(hp[1]);                                     \
        float2 f2 = __half22float2(hp[2]);                                     \
        float2 f3 = __half22float2(hp[3]);                                     \
        acc0.x = fmaf(W, f0.x, acc0.x); acc0.y = fmaf(W, f0.y, acc0.y);        \
        acc0.z = fmaf(W, f1.x, acc0.z); acc0.w = fmaf(W, f1.y, acc0.w);        \
        acc1.x = fmaf(W, f2.x, acc1.x); acc1.y = fmaf(W, f2.y, acc1.y);        \
        acc1.z = fmaf(W, f3.x, acc1.z); acc1.w = fmaf(W, f3.y, acc1.w);        \
    }

#define GATHER8_CORE(SScur, SDcur, ZHALF)                                      \
    int lane = threadIdx.x & 31;                                               \
    int l4   = lane & 3;                                                       \
    int gb   = lane & 28;          /* first lane of this 4-lane group */       \
    int warpid = blockIdx.x * (blockDim.x >> 5) + (threadIdx.x >> 5);          \
    int n = warpid * 8 + (lane >> 2);                                          \
    bool valid = (n < N);                                                      \
    int beg = 0, cnt = 0; float sd = 0.f;                                      \
    if (valid) {                                                               \
        beg = g_row[n] + g_bsum[n >> 9];                                       \
        cnt = (g_row[n + 1] + g_bsum[(n + 1) >> 9]) - beg;                     \
        sd  = SDcur[n];                                                        \
    }                                                                          \
    const uint4* Zv = (const uint4*)ZHALF;                                     \
    float4 acc0 = make_float4(0.f, 0.f, 0.f, 0.f);                             \
    float4 acc1 = make_float4(0.f, 0.f, 0.f, 0.f);                             \
    float den = 0.f;                                                           \
    int t = 0;                                                                 \
    for (; t + 4 <= cnt; t += 4) {                                             \
        int s0 = __ldg(g_esrc + beg + t);                                      \
        int s1 = __ldg(g_esrc + beg + t + 1);                                  \
        int s2 = __ldg(g_esrc + beg + t + 2);                                  \
        int s3 = __ldg(g_esrc + beg + t + 3);                                  \
        float x0 = __ldg(SScur + s0) + sd;                                     \
        float x1 = __ldg(SScur + s1) + sd;                                     \
        float x2 = __ldg(SScur + s2) + sd;                                     \
        float x3 = __ldg(SScur + s3) + sd;                                     \
        uint4 r0 = __ldg(Zv + s0 * 4 + l4);                                    \
        uint4 r1 = __ldg(Zv + s1 * 4 + l4);                                    \
        uint4 r2 = __ldg(Zv + s2 * 4 + l4);                                    \
        uint4 r3 = __ldg(Zv + s3 * 4 + l4);                                    \
        x0 = (x0 > 0.f) ? x0 : 0.01f * x0;                                     \
        x1 = (x1 > 0.f) ? x1 : 0.01f * x1;                                     \
        x2 = (x2 > 0.f) ? x2 : 0.01f * x2;                                     \
        x3 = (x3 > 0.f) ? x3 : 0.01f * x3;                                     \
        float w0 = __expf(x0);                                                 \
        float w1 = __expf(x1);                                                 \
        float w2 = __expf(x2);                                                 \
        float w3 = __expf(x3);                                                 \
        den += (w0 + w1) + (w2 + w3);                                          \
        FMA8(w0, r0)                                                           \
        FMA8(w1, r1)                                                           \
        FMA8(w2, r2)                                                           \
        FMA8(w3, r3)                                                           \
    }                                                                          \
    for (; t < cnt; t++) {                                                     \
        int s0 = __ldg(g_esrc + beg + t);                                      \
        float x0 = __ldg(SScur + s0) + sd;                                     \
        uint4 r0 = __ldg(Zv + s0 * 4 + l4);                                    \
        x0 = (x0 > 0.f) ? x0 : 0.01f * x0;                                     \
        float w0 = __expf(x0);                                                 \
        den += w0;                                                             \
        FMA8(w0, r0)                                                           \
    }                                                                          \
    float inv = 1.f / fmaxf(den, 1e-9f);                                       \
    float ha[8];                                                               \
    ha[0] = fmaxf(acc0.x * inv, 0.f); ha[1] = fmaxf(acc0.y * inv, 0.f);        \
    ha[2] = fmaxf(acc0.z * inv, 0.f); ha[3] = fmaxf(acc0.w * inv, 0.f);        \
    ha[4] = fmaxf(acc1.x * inv, 0.f); ha[5] = fmaxf(acc1.y * inv, 0.f);        \
    ha[6] = fmaxf(acc1.z * inv, 0.f); ha[7] = fmaxf(acc1.w * inv, 0.f);
// ha holds relu'd features (8*l4 .. 8*l4+7) of node n.

// ---------------------------------------------------------------------------
// Gather layer 1 + fused layer-2 node GEMM (z2 = h@W2, s_src2, s_dst2).
// ---------------------------------------------------------------------------
__global__ void __launch_bounds__(256, 5)
gather_fuse_L1L2_kernel(int N, const float* __restrict__ W2,
                        const float* __restrict__ a2)
{
    __shared__ float W2s[32 * 32];
    __shared__ float a2s[64];
    int tid0 = threadIdx.x;
    for (int i = tid0; i < 32 * 32; i += blockDim.x) W2s[i] = W2[i];
    if (tid0 < 64) a2s[tid0] = a2[tid0];
    __syncthreads();

    GATHER8_CORE(g_SS1, g_SD1, g_Zh)

    // z2[8 outputs: 8*l4 .. 8*l4+7] = sum_k h[k] * W2[k][outputs]
    const float4* W2v = (const float4*)W2s;    // row k = 8 float4s
    float z2[8];
    #pragma unroll
    for (int j = 0; j < 8; j++) z2[j] = 0.f;
    #pragma unroll
    for (int sl = 0; sl < 4; sl++) {
        #pragma unroll
        for (int i = 0; i < 8; i++) {
            float hk = __shfl_sync(0xffffffffu, ha[i], gb | sl);
            int k = sl * 8 + i;
            float4 wA = W2v[k * 8 + 2 * l4];
            float4 wB = W2v[k * 8 + 2 * l4 + 1];
            z2[0] = fmaf(hk, wA.x, z2[0]); z2[1] = fmaf(hk, wA.y, z2[1]);
            z2[2] = fmaf(hk, wA.z, z2[2]); z2[3] = fmaf(hk, wA.w, z2[3]);
            z2[4] = fmaf(hk, wB.x, z2[4]); z2[5] = fmaf(hk, wB.y, z2[5]);
            z2[6] = fmaf(hk, wB.z, z2[6]); z2[7] = fmaf(hk, wB.w, z2[7]);
        }
    }
    float ps = 0.f, pd = 0.f;
    #pragma unroll
    for (int j = 0; j < 8; j++) {
        ps = fmaf(z2[j], a2s[8 * l4 + j], ps);
        pd = fmaf(z2[j], a2s[32 + 8 * l4 + j], pd);
    }
    ps += __shfl_xor_sync(0xffffffffu, ps, 1);
    ps += __shfl_xor_sync(0xffffffffu, ps, 2);
    pd += __shfl_xor_sync(0xffffffffu, pd, 1);
    pd += __shfl_xor_sync(0xffffffffu, pd, 2);
    if (valid) {
        __half2 p0 = __floats2half2_rn(z2[0], z2[1]);
        __half2 p1 = __floats2half2_rn(z2[2], z2[3]);
        __half2 p2 = __floats2half2_rn(z2[4], z2[5]);
        __half2 p3 = __floats2half2_rn(z2[6], z2[7]);
        uint4 raw;
        raw.x = *reinterpret_cast<unsigned int*>(&p0);
        raw.y = *reinterpret_cast<unsigned int*>(&p1);
        raw.z = *reinterpret_cast<unsigned int*>(&p2);
        raw.w = *reinterpret_cast<unsigned int*>(&p3);
        ((uint4*)g_Z2h)[n * 4 + l4] = raw;
        if (l4 == 0) { g_SS2[n] = ps; g_SD2[n] = pd; }
    }
}

// ---------------------------------------------------------------------------
// Gather layer 2 + fused layer-3 node GEMM (scalar z3 = h.W3, s3 scalars).
// ---------------------------------------------------------------------------
__global__ void __launch_bounds__(256, 5)
gather_fuse_L2L3_kernel(int N, const float* __restrict__ W3,
                        const float* __restrict__ a3)
{
    __shared__ float W3s[32];
    __shared__ float a3s[2];
    int tid0 = threadIdx.x;
    if (tid0 < 32) W3s[tid0] = W3[tid0];
    if (tid0 < 2)  a3s[tid0] = a3[tid0];
    __syncthreads();

    GATHER8_CORE(g_SS2, g_SD2, g_Z2h)
    (void)gb;

    float z3 = 0.f;
    #pragma unroll
    for (int i = 0; i < 8; i++) z3 = fmaf(ha[i], W3s[8 * l4 + i], z3);
    z3 += __shfl_xor_sync(0xffffffffu, z3, 1);
    z3 += __shfl_xor_sync(0xffffffffu, z3, 2);
    if (valid && l4 == 0) {
        g_Zs[n]  = z3;
        g_SS3[n] = z3 * a3s[0];
        g_SD3[n] = z3 * a3s[1];
    }
}

// ---------------------------------------------------------------------------
// Final gather (dout=1): 8 nodes/warp, 4 lanes split each node's edges
// (esrc reads naturally coalesced per group), normalize + sigmoid -> output.
// ---------------------------------------------------------------------------
__global__ void __launch_bounds__(256)
gather1_kernel(int N, float* __restrict__ out)
{
    int lane = threadIdx.x & 31;
    int l4   = lane & 3;
    int warpid = blockIdx.x * (blockDim.x >> 5) + (threadIdx.x >> 5);
    int n = warpid * 8 + (lane >> 2);
    bool valid = (n < N);
    int beg = 0, end = 0; float sd = 0.f;
    if (valid) {
        beg = g_row[n] + g_bsum[n >> 9];
        end = g_row[n + 1] + g_bsum[(n + 1) >> 9];
        sd  = g_SD3[n];
    }

    float acc = 0.f, den = 0.f;
    for (int i = beg + l4; i < end; i += 4) {
        int s = __ldg(g_esrc + i);
        float x = __ldg(g_SS3 + s) + sd;
        x = (x > 0.f) ? x : 0.01f * x;
        float w = __expf(x);
        den += w;
        acc = fmaf(w, __ldg(g_Zs + s), acc);
    }
    den += __shfl_xor_sync(0xffffffffu, den, 1);
    den += __shfl_xor_sync(0xffffffffu, den, 2);
    acc += __shfl_xor_sync(0xffffffffu, acc, 1);
    acc += __shfl_xor_sync(0xffffffffu, acc, 2);
    if (valid && l4 == 0) {
        float v = acc / fmaxf(den, 1e-9f);
        out[n] = 1.f / (1.f + __expf(-v));
    }
}

// ===========================================================================
extern "C" void kernel_launch(void* const* d_in, const int* in_sizes, int n_in,
                              void* d_out, int out_size)
{
    const float* feat = (const float*)d_in[0];
    const int*   src  = (const int*)d_in[1];
    const int*   dst  = (const int*)d_in[2];
    const float* W1   = (const float*)d_in[3];
    const float* a1   = (const float*)d_in[4];
    const float* W2   = (const float*)d_in[5];
    const float* a2   = (const float*)d_in[6];
    const float* W3   = (const float*)d_in[7];
    const float* a3   = (const float*)d_in[8];

    const int E    = in_sizes[1];
    const int d1   = in_sizes[4] / 2;          // 32
    const int din1 = in_sizes[3] / d1;         // 128
    const int N    = in_sizes[0] / din1;       // 100000

    const int NT  = 256;
    const int WPB = NT / 32;                   // 8 warps/block
    float* out = (float*)d_out;

    // ---- fused dst-histogram + layer-1 node GEMM ----
    const int histBlocks = (E + NT - 1) / NT;
    const int gemmBlocks = (N + 4 * WPB - 1) / (4 * WPB);   // 4 nodes/warp
    {
        size_t shm = (size_t)(din1 * 32 + 64 + WPB * 4 * din1) * sizeof(float);
        hist_gemm_kernel<<<histBlocks + gemmBlocks, NT, shm>>>(
            dst, E, histBlocks, feat, W1, a1, N, din1);
    }

    // ---- CSR scan (decoupled, single kernel) + scatter (fused apply) ----
    const int NB = (N + SCAN_B - 1) / SCAN_B;
    scan1_kernel<<<NB, SCAN_B>>>(N, E, NB);
    scatter_kernel<<<histBlocks, NT>>>(src, dst, E);

    // ---- Gather chains (8 nodes/warp, 4 lanes/node, fp16 Z, 4-deep MLP) ----
    const int octs = (N + 7) / 8;
    const int gBlocks = (octs + WPB - 1) / WPB;
    gather_fuse_L1L2_kernel<<<gBlocks, NT>>>(N, W2, a2);
    gather_fuse_L2L3_kernel<<<gBlocks, NT>>>(N, W3, a3);
    gather1_kernel<<<gBlocks, NT>>>(N, out);
}